// round 11
// baseline (speedup 1.0000x reference)
#include <cuda_runtime.h>
#include <cstdint>
#include <cstddef>

// ---------------- configuration ----------------
#define THREADS 256
#define BT 32          // batch rows per CTA
// 8 warps; warp w exclusively owns batch rows 4w..4w+3 for the entire
// 20-step recurrence. No __syncthreads in the step loop — only __syncwarp.
// Per-warp tiling: lane = ry1*16 + cx; RM=2 rows (rw = 4w + 2*ry1),
// CN=8 cols for N=128 GEMMs, CN=4 for N=64 GEMMs.

// smem strides (floats); all ≡4 mod 32 -> conflict-free 16B column walks.
#define LD1 116        // W1^T K=112 pad 116
#define LD2 132        // W2^T K=128
#define LD3 132        // W3^T K=128
#define LDD 68         // Wd1^T/Wd2^T K=64
#define HS  68         // h stride
#define XMS 68         // xm/zd shared region stride (x:0-31, m:32-47; zd:0-63)
#define ZS  132        // z stride (128 pad 132)

// smem layout (float offsets)
#define O_W1T 0
#define O_W2T (O_W1T + 128*LD1)
#define O_W3T (O_W2T + 128*LD2)
#define O_WD1 (O_W3T + 64*LD3)
#define O_WD2 (O_WD1 + 64*LDD)
#define O_B1  (O_WD2 + 64*LDD)
#define O_B2  (O_B1 + 128)
#define O_B3  (O_B2 + 128)
#define O_BD1 (O_B3 + 64)
#define O_BD2 (O_BD1 + 64)
#define O_SCL (O_BD2 + 64)
#define O_H   (O_SCL + 64)
#define O_XM  (O_H + BT*HS)              // xm gather region == ZD (warp-private rows)
#define O_ZD  O_XM
#define O_Z   (O_XM + BT*XMS)
#define O_IDX (O_Z + BT*ZS)
#define SMEM_FLOATS (O_IDX + 32)         // 232,064 B

// packed dual-fp32 FMA (Blackwell f32x2). d.lo += a.lo*b.lo; d.hi += a.hi*b.hi
#define FFMA2(d, a, b) asm("fma.rn.f32x2 %0, %1, %2, %0;" : "+l"(d) : "l"(a), "l"(b))

__device__ __forceinline__ float hadd2(unsigned long long p) {
    float lo, hi;
    asm("mov.b64 {%0,%1}, %2;" : "=f"(lo), "=f"(hi) : "l"(p));
    return lo + hi;
}

// Plain MAC loop (RMT rows x CN cols), .x pass then .y pass per k-quad.
template<int K, int RMT, int LDA, int LDB, int CN>
__device__ __forceinline__ void gemm_acc(const float* __restrict__ A,
                                         const float* __restrict__ Bt,
                                         unsigned long long (&acc)[RMT][CN]) {
#pragma unroll 4
    for (int k = 0; k < K; k += 4) {
        ulonglong2 a[RMT], b[CN];
#pragma unroll
        for (int r = 0; r < RMT; r++)
            a[r] = *reinterpret_cast<const ulonglong2*>(A + r*LDA + k);
#pragma unroll
        for (int c = 0; c < CN; c++)
            b[c] = *reinterpret_cast<const ulonglong2*>(Bt + c*16*LDB + k);
#pragma unroll
        for (int c = 0; c < CN; c++)
#pragma unroll
            for (int r = 0; r < RMT; r++)
                FFMA2(acc[r][c], a[r].x, b[c].x);
#pragma unroll
        for (int c = 0; c < CN; c++)
#pragma unroll
            for (int r = 0; r < RMT; r++)
                FFMA2(acc[r][c], a[r].y, b[c].y);
    }
}

// Fused MAC, shared A feeding two B streams / acc sets.
template<int K, int RMT, int LDA, int LDB1, int LDB2, int CN1, int CN2>
__device__ __forceinline__ void gemm_fused_sA(const float* __restrict__ A,
                                              const float* __restrict__ B1,
                                              const float* __restrict__ B2,
                                              unsigned long long (&acc1)[RMT][CN1],
                                              unsigned long long (&acc2)[RMT][CN2]) {
#pragma unroll 4
    for (int k = 0; k < K; k += 4) {
        ulonglong2 a[RMT], b1r[CN1], b2r[CN2];
#pragma unroll
        for (int r = 0; r < RMT; r++)
            a[r] = *reinterpret_cast<const ulonglong2*>(A + r*LDA + k);
#pragma unroll
        for (int c = 0; c < CN1; c++)
            b1r[c] = *reinterpret_cast<const ulonglong2*>(B1 + c*16*LDB1 + k);
#pragma unroll
        for (int c = 0; c < CN2; c++)
            b2r[c] = *reinterpret_cast<const ulonglong2*>(B2 + c*16*LDB2 + k);
#pragma unroll
        for (int c = 0; c < CN1; c++)
#pragma unroll
            for (int r = 0; r < RMT; r++) FFMA2(acc1[r][c], a[r].x, b1r[c].x);
#pragma unroll
        for (int c = 0; c < CN2; c++)
#pragma unroll
            for (int r = 0; r < RMT; r++) FFMA2(acc2[r][c], a[r].x, b2r[c].x);
#pragma unroll
        for (int c = 0; c < CN1; c++)
#pragma unroll
            for (int r = 0; r < RMT; r++) FFMA2(acc1[r][c], a[r].y, b1r[c].y);
#pragma unroll
        for (int c = 0; c < CN2; c++)
#pragma unroll
            for (int r = 0; r < RMT; r++) FFMA2(acc2[r][c], a[r].y, b2r[c].y);
    }
}

// Fused MAC, two independent A/B streams.
template<int K, int RMT, int LDA1, int LDA2, int LDB1, int LDB2, int CN>
__device__ __forceinline__ void gemm_fused_2A(const float* __restrict__ A1,
                                              const float* __restrict__ A2,
                                              const float* __restrict__ B1,
                                              const float* __restrict__ B2,
                                              unsigned long long (&acc1)[RMT][CN],
                                              unsigned long long (&acc2)[RMT][CN]) {
#pragma unroll 4
    for (int k = 0; k < K; k += 4) {
        ulonglong2 a1[RMT], a2[RMT], b1r[CN], b2r[CN];
#pragma unroll
        for (int r = 0; r < RMT; r++) {
            a1[r] = *reinterpret_cast<const ulonglong2*>(A1 + r*LDA1 + k);
            a2[r] = *reinterpret_cast<const ulonglong2*>(A2 + r*LDA2 + k);
        }
#pragma unroll
        for (int c = 0; c < CN; c++) {
            b1r[c] = *reinterpret_cast<const ulonglong2*>(B1 + c*16*LDB1 + k);
            b2r[c] = *reinterpret_cast<const ulonglong2*>(B2 + c*16*LDB2 + k);
        }
#pragma unroll
        for (int c = 0; c < CN; c++)
#pragma unroll
            for (int r = 0; r < RMT; r++) FFMA2(acc1[r][c], a1[r].x, b1r[c].x);
#pragma unroll
        for (int c = 0; c < CN; c++)
#pragma unroll
            for (int r = 0; r < RMT; r++) FFMA2(acc2[r][c], a2[r].x, b2r[c].x);
#pragma unroll
        for (int c = 0; c < CN; c++)
#pragma unroll
            for (int r = 0; r < RMT; r++) FFMA2(acc1[r][c], a1[r].y, b1r[c].y);
#pragma unroll
        for (int c = 0; c < CN; c++)
#pragma unroll
            for (int r = 0; r < RMT; r++) FFMA2(acc2[r][c], a2[r].y, b2r[c].y);
    }
}

extern "C" __global__ void __launch_bounds__(THREADS, 1)
nsde_kernel(const float* __restrict__ x_path, const float* __restrict__ macro_path,
            const float* __restrict__ t_span, const float* __restrict__ noise,
            const float* __restrict__ W1,  const float* __restrict__ b1,
            const float* __restrict__ W2,  const float* __restrict__ b2,
            const float* __restrict__ W3,  const float* __restrict__ b3,
            const float* __restrict__ Wd1, const float* __restrict__ bd1,
            const float* __restrict__ Wd2, const float* __restrict__ bd2,
            const float* __restrict__ scale,
            const float* __restrict__ Wr1, const float* __restrict__ br1,
            const float* __restrict__ Wr2, const float* __restrict__ br2,
            float* __restrict__ out, int B, int STEPS)
{
    extern __shared__ __align__(16) float sm[];
    const int tid  = threadIdx.x;
    const int wid  = tid >> 5;           // warp 0..7; owns rows 4w..4w+3
    const int lane = tid & 31;
    const int ry1  = lane >> 4;          // 0/1: row pair within warp
    const int cx   = lane & 15;          // 16 column groups
    const int rw   = wid*4 + 2*ry1;      // lane's first row (RM=2)
    const int b0   = blockIdx.x * BT;

    // gather ownership (warp-private rows)
    const int xr = wid*4 + (lane >> 3), xq = lane & 7;        // x: 4 rows x 8 f4
    const int mr = wid*4 + (lane >> 2), mq = lane & 3;        // m: lanes<16

    // ---- one-time: load + transpose weights into smem ----
    for (int i = tid; i < 112*128; i += THREADS) {
        int k = i >> 7, n = i & 127;
        sm[O_W1T + n*LD1 + k] = W1[i];
    }
    for (int i = tid; i < 128*128; i += THREADS) {
        int k = i >> 7, n = i & 127;
        sm[O_W2T + n*LD2 + k] = W2[i];
    }
    for (int i = tid; i < 128*64; i += THREADS) {
        int k = i >> 6, n = i & 63;
        sm[O_W3T + n*LD3 + k] = W3[i];
    }
    for (int i = tid; i < 64*64; i += THREADS) {
        int k = i >> 6, n = i & 63;
        sm[O_WD1 + n*LDD + k] = Wd1[i];
        sm[O_WD2 + n*LDD + k] = Wd2[i];
    }
    if (tid < 128) { sm[O_B1 + tid] = b1[tid]; sm[O_B2 + tid] = b2[tid]; }
    if (tid < 64)  {
        sm[O_B3 + tid] = b3[tid]; sm[O_BD1 + tid] = bd1[tid];
        sm[O_BD2 + tid] = bd2[tid]; sm[O_SCL + tid] = scale[tid];
    }
    for (int i = tid; i < BT*HS; i += THREADS) sm[O_H + i] = 0.0f;

    if (tid < STEPS) {
        float tn = t_span[tid] / t_span[STEPS];
        int idx  = (int)(tn * 255.0f);
        reinterpret_cast<int*>(sm + O_IDX)[tid] = max(0, min(idx, 255));
    }
    __syncthreads();   // the ONLY cross-warp barrier before the readout

    const float sqdt = sqrtf(0.05f);

    // prologue gather for step 0 (registers)
    float4 xv, mv;
    {
        int idx = reinterpret_cast<const int*>(sm + O_IDX)[0];
        xv = *reinterpret_cast<const float4*>(
                 x_path + ((size_t)(b0 + xr) * 256 + idx) * 32 + 4*xq);
        if (lane < 16)
            mv = *reinterpret_cast<const float4*>(
                     macro_path + ((size_t)(b0 + mr) * 256 + idx) * 16 + 4*mq);
    }

    for (int s = 0; s < STEPS; s++) {
        // ---- store pre-gathered xm into warp-private rows (zd reads of the
        //      previous step are ordered by the loop-end __syncwarp) ----
        *reinterpret_cast<float4*>(&sm[O_XM + xr*XMS + 4*xq]) = xv;
        if (lane < 16)
            *reinterpret_cast<float4*>(&sm[O_XM + mr*XMS + 32 + 4*mq]) = mv;

        // ---- prefetch this step's noise (2 rows x 4 cols) ----
        float nz[2][4];
#pragma unroll
        for (int r = 0; r < 2; r++)
#pragma unroll
            for (int c = 0; c < 4; c++)
                nz[r][c] = noise[((size_t)s * B + (b0 + rw + r)) * 64 + (cx + 16*c)];

        __syncwarp();  // W0: xm visible; prior-step h update visible

        // ==== P0: G1 (z1, CN=8) fused with Gd1 (zd accs, CN=4), shared A=h ==
        unsigned long long accd[2][4] = {};
        {
            unsigned long long acc[2][8] = {};
            gemm_fused_sA<64, 2, HS, LD1, LDD, 8, 4>(
                sm + O_H + rw*HS, sm + O_W1T + cx*LD1, sm + O_WD1 + cx*LDD,
                acc, accd);
            gemm_acc<48, 2, XMS, LD1, 8>(sm + O_XM + rw*XMS,
                                         sm + O_W1T + cx*LD1 + 64, acc);
            __syncwarp();  // W1: all xm reads done before zd overwrites region
#pragma unroll
            for (int c = 0; c < 8; c++) {
                int col = cx + 16*c;
                float bias = sm[O_B1 + col];
#pragma unroll
                for (int r = 0; r < 2; r++)
                    sm[O_Z + (rw+r)*ZS + col] = fmaxf(hadd2(acc[r][c]) + bias, 0.0f);
            }
            // finalize zd into the (now dead) XM region
#pragma unroll
            for (int c = 0; c < 4; c++) {
                int col = cx + 16*c;
                float bdv = sm[O_BD1 + col];
#pragma unroll
                for (int r = 0; r < 2; r++)
                    sm[O_ZD + (rw+r)*XMS + col] =
                        fmaxf(hadd2(accd[r][c]) + bdv, 0.0f);
            }
        }
        __syncwarp();  // W2: z1 + zd visible within warp

        // ==== P1: G2 (z2 = relu(z1 @ W2 + b2), in-place, K=128) ====
        {
            unsigned long long acc[2][8] = {};
            gemm_acc<128, 2, ZS, LD2, 8>(sm + O_Z + rw*ZS, sm + O_W2T + cx*LD2, acc);
            __syncwarp();  // W3: all z1 reads done -> safe in-place overwrite
#pragma unroll
            for (int c = 0; c < 8; c++) {
                int col = cx + 16*c;
                float bias = sm[O_B2 + col];
#pragma unroll
                for (int r = 0; r < 2; r++)
                    sm[O_Z + (rw+r)*ZS + col] = fmaxf(hadd2(acc[r][c]) + bias, 0.0f);
            }
        }

        // ---- gather step s+1's x/m in the FMA shadow of P2 ----
        if (s + 1 < STEPS) {
            int idx = reinterpret_cast<const int*>(sm + O_IDX)[s+1];
            xv = *reinterpret_cast<const float4*>(
                     x_path + ((size_t)(b0 + xr) * 256 + idx) * 32 + 4*xq);
            if (lane < 16)
                mv = *reinterpret_cast<const float4*>(
                         macro_path + ((size_t)(b0 + mr) * 256 + idx) * 16 + 4*mq);
        }
        __syncwarp();  // W4: z2 visible within warp

        // ==== P2: G3 (drift, K=128) fused with Gd2 (diff, K=64); h update ====
        {
            unsigned long long acc3[2][4] = {};
            unsigned long long accD[2][4] = {};
            gemm_fused_2A<64, 2, ZS, XMS, LD3, LDD, 4>(
                sm + O_Z + rw*ZS, sm + O_ZD + rw*XMS,
                sm + O_W3T + cx*LD3, sm + O_WD2 + cx*LDD,
                acc3, accD);
            gemm_acc<64, 2, ZS, LD3, 4>(sm + O_Z + rw*ZS + 64,
                                        sm + O_W3T + cx*LD3 + 64, acc3);
#pragma unroll
            for (int c = 0; c < 4; c++) {
                int col = cx + 16*c;
                float b3v = sm[O_B3 + col];
                float bdv = sm[O_BD2 + col];
                float scl = sm[O_SCL + col];
#pragma unroll
                for (int r = 0; r < 2; r++) {
                    float drift = hadd2(acc3[r][c]) + b3v;
                    float u     = hadd2(accD[r][c]) + bdv;
                    float sig   = 1.0f / (1.0f + __expf(-u));
                    sm[O_H + (rw+r)*HS + col] +=
                        drift*0.05f + scl*sig*sqdt*nz[r][c];
                }
            }
        }
        __syncwarp();  // W5: zd/z2 reads + h writes ordered before next step
    }
    __syncthreads();   // final h visible to all warps for the readout

    // ---- readout: z = relu(h @ Wr1 + br1); out = z @ Wr2 + br2 ----
    for (int i = tid; i < 256; i += THREADS) {
        int r = i >> 3, g = i & 7;
        float z0 = br1[4*g], z1 = br1[4*g+1], z2 = br1[4*g+2], z3 = br1[4*g+3];
        const float* hrow = sm + O_H + r*HS;
#pragma unroll 4
        for (int k = 0; k < 64; k++) {
            float a = hrow[k];
            float4 w = *reinterpret_cast<const float4*>(Wr1 + k*32 + 4*g);
            z0 += a*w.x; z1 += a*w.y; z2 += a*w.z; z3 += a*w.w;
        }
        sm[O_Z + r*ZS + 4*g + 0] = fmaxf(z0, 0.0f);
        sm[O_Z + r*ZS + 4*g + 1] = fmaxf(z1, 0.0f);
        sm[O_Z + r*ZS + 4*g + 2] = fmaxf(z2, 0.0f);
        sm[O_Z + r*ZS + 4*g + 3] = fmaxf(z3, 0.0f);
    }
    __syncthreads();
    if (tid < 64) {
        int r = tid >> 1, o = tid & 1;
        float acc = br2[o];
#pragma unroll 4
        for (int k = 0; k < 32; k++)
            acc += sm[O_Z + r*ZS + k] * Wr2[2*k + o];
        out[(size_t)o * B + b0 + r] = acc;
    }
}

extern "C" void kernel_launch(void* const* d_in, const int* in_sizes, int n_in,
                              void* d_out, int out_size) {
    const float* x_path     = (const float*)d_in[0];
    const float* macro_path = (const float*)d_in[1];
    const float* t_span     = (const float*)d_in[2];
    const float* noise      = (const float*)d_in[3];
    const float* W1  = (const float*)d_in[4];
    const float* b1  = (const float*)d_in[5];
    const float* W2  = (const float*)d_in[6];
    const float* b2  = (const float*)d_in[7];
    const float* W3  = (const float*)d_in[8];
    const float* b3  = (const float*)d_in[9];
    const float* Wd1 = (const float*)d_in[10];
    const float* bd1 = (const float*)d_in[11];
    const float* Wd2 = (const float*)d_in[12];
    const float* bd2 = (const float*)d_in[13];
    const float* scale = (const float*)d_in[14];
    const float* Wr1 = (const float*)d_in[15];
    const float* br1 = (const float*)d_in[16];
    const float* Wr2 = (const float*)d_in[17];
    const float* br2 = (const float*)d_in[18];
    float* out = (float*)d_out;

    int B     = in_sizes[0] / (256 * 32);   // x_path (B, 256, 32)
    int STEPS = in_sizes[3] / (B * 64);     // noise (STEPS, B, 64)

    size_t smem_bytes = (size_t)SMEM_FLOATS * sizeof(float);
    cudaFuncSetAttribute(nsde_kernel,
                         cudaFuncAttributeMaxDynamicSharedMemorySize,
                         (int)smem_bytes);
    nsde_kernel<<<B / BT, THREADS, smem_bytes>>>(
        x_path, macro_path, t_span, noise,
        W1, b1, W2, b2, W3, b3, Wd1, bd1, Wd2, bd2,
        scale, Wr1, br1, Wr2, br2, out, B, STEPS);
}